// round 15
// baseline (speedup 1.0000x reference)
#include <cuda_runtime.h>
#include <cstdint>
#include <math.h>

// Problem constants
#define Bb   8
#define Tt   2048
#define Dd   1024
#define Hh   8
#define Cc   64
#define DVv  128
#define Mm   (Bb*Tt)
#define PSTR  768
#define CH   16
#define QVS  1536
#define SST  224          // scan smem per-step stride (a64|k64|q64|v16|pad)

// ---------------- scratch -------------------------------------------------
__device__ float g_xn  [(size_t)Mm*Dd];       // tf32-rounded layernorm out
__device__ float g_wall[(size_t)PSTR*Dd];     // tf32-rounded proj weights
__device__ float g_hw  [(size_t)QVS*Cc];      // tf32-rounded head weights
__device__ float g_wo  [(size_t)Dd*Dd];       // tf32-rounded output weights
__device__ float g_proj[(size_t)Mm*PSTR];     // qlat|kn|vlat|alpha (q/v tf32-rounded)
__device__ float g_qv  [(size_t)Mm*QVS];
__device__ float g_o   [(size_t)Mm*Dd];       // tf32-rounded scan out

__device__ __forceinline__ uint32_t f2tf32(float f) {
    uint32_t u;
    asm volatile("cvt.rna.tf32.f32 %0, %1;" : "=r"(u) : "f"(f));
    return u;
}
__device__ __forceinline__ float tf32r(float f) { return __uint_as_float(f2tf32(f)); }

__device__ __forceinline__ uint32_t smem_u32(const void* p) {
    uint32_t a;
    asm("{ .reg .u64 t; cvta.to.shared.u64 t, %1; cvt.u32.u64 %0, t; }" : "=r"(a) : "l"(p));
    return a;
}
__device__ __forceinline__ void cp16(uint32_t dst, const void* src) {
    asm volatile("cp.async.cg.shared.global [%0], [%1], 16;" :: "r"(dst), "l"(src));
}
#define CP_COMMIT() asm volatile("cp.async.commit_group;" ::: "memory")
#define CP_WAIT(n)  asm volatile("cp.async.wait_group %0;" :: "n"(n) : "memory")

// ---------------- 1. fused LayerNorm + weight prep -------------------------
#define WALL_ELEMS (PSTR*Dd)
#define HW_ELEMS   (QVS*Cc)
#define WO_ELEMS   (Dd*Dd)
#define PREP_TOTAL (WALL_ELEMS + HW_ELEMS + WO_ELEMS)
#define PREP_BLOCKS ((PREP_TOTAL + 255) / 256)

__global__ __launch_bounds__(256)
void ln_prep_kernel(const float* __restrict__ x, const float* __restrict__ gamma,
                    const float* __restrict__ beta,
                    const float* __restrict__ Wq, const float* __restrict__ Wk,
                    const float* __restrict__ Wv, const float* __restrict__ Wa,
                    const float* __restrict__ Qc, const float* __restrict__ Vc,
                    const float* __restrict__ Wo)
{
    int tid = threadIdx.x;
    if (blockIdx.x >= Mm) {
        int i = (blockIdx.x - Mm) * 256 + tid;
        if (i < WALL_ELEMS) {
            int row = i >> 10, col = i & 1023;
            float val;
            if      (row <  64) val = Wq[(size_t)row       *1024 + col];
            else if (row < 128) val = Wk[(size_t)(row- 64) *1024 + col];
            else if (row < 192) val = Wv[(size_t)(row-128) *1024 + col];
            else if (row < 704) val = Wa[(size_t)(row-192) *1024 + col];
            else                val = 0.f;
            g_wall[i] = tf32r(val);
        } else if (i < WALL_ELEMS + HW_ELEMS) {
            int j = i - WALL_ELEMS;
            int n = j >> 6, c = j & 63;
            float val;
            if (n < 512) { int h = n >> 6, e = n & 63;  val = Qc[(size_t)h*Cc*Cc + (size_t)c*Cc + e]; }
            else { int nn = n - 512; int h = nn >> 7, d = nn & 127; val = Vc[(size_t)h*Cc*DVv + (size_t)c*DVv + d]; }
            g_hw[j] = tf32r(val);
        } else if (i < PREP_TOTAL) {
            int j = i - WALL_ELEMS - HW_ELEMS;
            g_wo[j] = tf32r(Wo[j]);
        }
        return;
    }

    int row = blockIdx.x;
    const float4* xr = (const float4*)(x + (size_t)row*Dd);
    float4 v = xr[tid];
    float s  = v.x + v.y + v.z + v.w;
    float s2 = v.x*v.x + v.y*v.y + v.z*v.z + v.w*v.w;
    #pragma unroll
    for (int o = 16; o > 0; o >>= 1) {
        s  += __shfl_xor_sync(0xffffffffu, s,  o);
        s2 += __shfl_xor_sync(0xffffffffu, s2, o);
    }
    __shared__ float r1[8], r2[8];
    int w = tid >> 5, l = tid & 31;
    if (l == 0) { r1[w] = s; r2[w] = s2; }
    __syncthreads();
    s = 0.f; s2 = 0.f;
    #pragma unroll
    for (int i = 0; i < 8; i++) { s += r1[i]; s2 += r2[i]; }
    float mu  = s * (1.f/Dd);
    float var = s2 * (1.f/Dd) - mu*mu;
    float inv = rsqrtf(var + 1e-5f);
    float4 g  = ((const float4*)gamma)[tid];
    float4 be = ((const float4*)beta)[tid];
    float4 o;
    o.x = tf32r((v.x - mu)*inv*g.x + be.x);
    o.y = tf32r((v.y - mu)*inv*g.y + be.y);
    o.z = tf32r((v.z - mu)*inv*g.z + be.z);
    o.w = tf32r((v.w - mu)*inv*g.w + be.w);
    ((float4*)(g_xn + (size_t)row*Dd))[tid] = o;
}

// ---------------- 2. TF32 GEMM, 64x64 warp tile, cp.async (R12 form) ------
__device__ __forceinline__ void mma_tf32(float c[4], const uint32_t a[4], const uint32_t b[2]) {
    asm volatile(
        "mma.sync.aligned.m16n8k8.row.col.f32.tf32.tf32.f32 "
        "{%0,%1,%2,%3}, {%4,%5,%6,%7}, {%8,%9}, {%0,%1,%2,%3};\n"
        : "+f"(c[0]), "+f"(c[1]), "+f"(c[2]), "+f"(c[3])
        : "r"(a[0]), "r"(a[1]), "r"(a[2]), "r"(a[3]), "r"(b[0]), "r"(b[1]));
}

__global__ __launch_bounds__(128, 3)
void gemm_tf32(int K, int lda, int ldy, int mode,
               const float* __restrict__ A,
               const float* __restrict__ W,
               float* __restrict__ Y,
               const float* __restrict__ resid,
               const float* __restrict__ bias)
{
    __shared__ uint32_t As[2][128*20];
    __shared__ uint32_t Bs[2][128*20];

    int tid  = threadIdx.x;
    int lane = tid & 31, warp = tid >> 5;
    int wm = warp & 1, wn = warp >> 1;
    int g  = lane >> 2, tig = lane & 3;
    int row0 = blockIdx.y * 128;
    int col0 = blockIdx.x * 128;
    if (mode == 3 && col0 >= 512) A += 128;

    uint32_t asb = smem_u32(As), bsb = smem_u32(Bs);
    const float* Abase = A + (size_t)row0 * lda;
    const float* Bbase = W + (size_t)col0 * K;

    float acc[4][8][4];
    #pragma unroll
    for (int i = 0; i < 4; i++)
        #pragma unroll
        for (int j = 0; j < 8; j++)
            #pragma unroll
            for (int e = 0; e < 4; e++) acc[i][j][e] = 0.f;

    #pragma unroll
    for (int i = 0; i < 4; i++) {
        int s = tid + i*128;
        int row = s >> 2, q = s & 3;
        uint32_t soff = (uint32_t)(row*20 + q*4) * 4;
        cp16(asb + soff, Abase + (size_t)row*lda + q*4);
        cp16(bsb + soff, Bbase + (size_t)row*K   + q*4);
    }
    CP_COMMIT();

    int NC = K >> 4;
    for (int c = 0; c < NC; c++) {
        int buf = c & 1;
        if (c + 1 < NC) {
            int nb = buf ^ 1;
            int k0 = (c + 1) << 4;
            uint32_t ab = asb + (uint32_t)nb * (128*20*4);
            uint32_t bb = bsb + (uint32_t)nb * (128*20*4);
            #pragma unroll
            for (int i = 0; i < 4; i++) {
                int s = tid + i*128;
                int row = s >> 2, q = s & 3;
                uint32_t soff = (uint32_t)(row*20 + q*4) * 4;
                cp16(ab + soff, Abase + (size_t)row*lda + k0 + q*4);
                cp16(bb + soff, Bbase + (size_t)row*K   + k0 + q*4);
            }
            CP_COMMIT();
            CP_WAIT(1);
        } else {
            CP_WAIT(0);
        }
        __syncthreads();

        const uint32_t* Ab  = As[buf];
        const uint32_t* Bb_ = Bs[buf];
        #pragma unroll
        for (int ks = 0; ks < 16; ks += 8) {
            uint32_t af[4][4], bf[8][2];
            #pragma unroll
            for (int i = 0; i < 4; i++) {
                int base = (wm*64 + i*16 + g)*20 + ks + tig;
                af[i][0] = Ab[base];
                af[i][1] = Ab[base + 8*20];
                af[i][2] = Ab[base + 4];
                af[i][3] = Ab[base + 8*20 + 4];
            }
            #pragma unroll
            for (int j = 0; j < 8; j++) {
                int base = (wn*64 + j*8 + g)*20 + ks + tig;
                bf[j][0] = Bb_[base];
                bf[j][1] = Bb_[base + 4];
            }
            #pragma unroll
            for (int i = 0; i < 4; i++)
                #pragma unroll
                for (int j = 0; j < 8; j++)
                    mma_tf32(acc[i][j], af[i], bf[j]);
        }
        __syncthreads();
    }

    bool knorm_warp = (mode == 2) && (col0 + wn*64 == 64);
    #pragma unroll
    for (int i = 0; i < 4; i++) {
        #pragma unroll
        for (int half = 0; half < 2; half++) {
            int m = row0 + wm*64 + i*16 + g + half*8;
            float scale = 1.f;
            if (knorm_warp) {
                float s = 0.f;
                #pragma unroll
                for (int j = 0; j < 8; j++) {
                    float e0 = acc[i][j][half*2], e1 = acc[i][j][half*2+1];
                    s = fmaf(e0, e0, s); s = fmaf(e1, e1, s);
                }
                s += __shfl_xor_sync(0xffffffffu, s, 1);
                s += __shfl_xor_sync(0xffffffffu, s, 2);
                scale = 1.f / fmaxf(sqrtf(s), 1e-12f);
            }
            #pragma unroll
            for (int j = 0; j < 8; j++) {
                int n0 = col0 + wn*64 + j*8 + tig*2;
                float2 val = make_float2(acc[i][j][half*2], acc[i][j][half*2+1]);
                if (mode == 1) {
                    const float2 r = *(const float2*)(resid + (size_t)m*ldy + n0);
                    val.x += r.x; val.y += r.y;
                } else if (mode == 2) {
                    if (knorm_warp) {
                        val.x *= scale; val.y *= scale;
                    } else if (n0 < 192) {
                        val.x = tf32r(val.x); val.y = tf32r(val.y);
                    } else if (n0 < 704) {
                        float2 bb = *(const float2*)(bias + n0 - 192);
                        val.x = 1.f / (1.f + expf(-(val.x + bb.x)));
                        val.y = 1.f / (1.f + expf(-(val.y + bb.y)));
                    }
                }
                *(float2*)(Y + (size_t)m*ldy + n0) = val;
            }
        }
    }
}

// ---------------- 3. recurrent scan: 512 blocks x 128 thr (8c x 1v) -------
// Block = (bh, vgroup of 16 v). Thread = (vi 0..15, cg 0..7) -> S[8].
// Per chunk stage CH steps of [a64|k64|q64|v16] (stride SST) into 2 buffers.
__global__ __launch_bounds__(128)
void scan_kernel()
{
    int blk = blockIdx.x;
    int bh  = blk >> 3;
    int vg8 = blk & 7;          // which 16-v group of the 128 head dims
    int b = bh >> 3, h = bh & 7;
    int tid = threadIdx.x;
    int vi = tid >> 3;          // 0..15
    int cg = tid & 7;           // 0..7 -> c = cg*8 .. cg*8+7
    const float* qp = g_qv + (size_t)(b*Tt)*QVS + h*64;
    const float* vp = g_qv + (size_t)(b*Tt)*QVS + 512 + h*128 + vg8*16;
    const float* pp = g_proj + (size_t)b * Tt * PSTR;
    float* op = g_o + (size_t)b * Tt * Dd + h*DVv + vg8*16 + vi;

    // chunk loader: 52 float4 per step (a16|k16|q16|v4) x CH = 832 float4
    // flat f = i*128 + tid, i = 0..6 (last iteration partially valid)
    const float* lsrc[7];
    size_t ladv[7];
    int ldst[7];
    bool lval[7];
    #pragma unroll
    for (int i = 0; i < 7; i++) {
        int f = i * 128 + tid;
        lval[i] = (f < 832);
        int fc = lval[i] ? f : 0;
        int r = fc / 52, p = fc % 52;
        if (p < 16)      { lsrc[i] = pp + (size_t)r*PSTR + 192 + h*64 + p*4;  ladv[i] = (size_t)CH*PSTR; }
        else if (p < 32) { lsrc[i] = pp + (size_t)r*PSTR + 64 + (p-16)*4;     ladv[i] = (size_t)CH*PSTR; }
        else if (p < 48) { lsrc[i] = qp + (size_t)r*QVS + (p-32)*4;           ladv[i] = (size_t)CH*QVS;  }
        else             { lsrc[i] = vp + (size_t)r*QVS + (p-48)*4;           ladv[i] = (size_t)CH*QVS;  }
        ldst[i] = r*SST + (p < 48 ? p*4 : 192 + (p-48)*4);
    }

    __shared__ __align__(16) float sh[2][CH*SST];
    float S[8];
    #pragma unroll
    for (int i = 0; i < 8; i++) S[i] = 0.f;

    #pragma unroll
    for (int i = 0; i < 7; i++)
        if (lval[i]) *(float4*)&sh[0][ldst[i]] = *(const float4*)lsrc[i];
    __syncthreads();

    int buf = 0;
    for (int c = 0; c < Tt/CH; c++) {
        float4 pf[7];
        bool more = (c + 1) < (Tt/CH);
        if (more) {
            #pragma unroll
            for (int i = 0; i < 7; i++)
                if (lval[i]) pf[i] = *(const float4*)(lsrc[i] + (size_t)(c+1)*ladv[i]);
        }
        const float* cb = sh[buf];
        #pragma unroll 4
        for (int r = 0; r < CH; r++) {
            const float* base = cb + r*SST;
            float4 a0 = *(const float4*)(base +       cg*8);
            float4 a1 = *(const float4*)(base +       cg*8 + 4);
            float4 k0 = *(const float4*)(base +  64 + cg*8);
            float4 k1 = *(const float4*)(base +  64 + cg*8 + 4);
            float4 q0 = *(const float4*)(base + 128 + cg*8);
            float4 q1 = *(const float4*)(base + 128 + cg*8 + 4);
            float vt = base[192 + vi];
            float acc = 0.f;

            S[0] = fmaf(a0.x, S[0], k0.x*vt); acc = fmaf(q0.x, S[0], acc);
            S[1] = fmaf(a0.y, S[1], k0.y*vt); acc = fmaf(q0.y, S[1], acc);
            S[2] = fmaf(a0.z, S[2], k0.z*vt); acc = fmaf(q0.z, S[2], acc);
            S[3] = fmaf(a0.w, S[3], k0.w*vt); acc = fmaf(q0.w, S[3], acc);
            S[4] = fmaf(a1.x, S[4], k1.x*vt); acc = fmaf(q1.x, S[4], acc);
            S[5] = fmaf(a1.y, S[5], k1.y*vt); acc = fmaf(q1.y, S[5], acc);
            S[6] = fmaf(a1.z, S[6], k1.z*vt); acc = fmaf(q1.z, S[6], acc);
            S[7] = fmaf(a1.w, S[7], k1.w*vt); acc = fmaf(q1.w, S[7], acc);

            acc += __shfl_xor_sync(0xffffffffu, acc, 1);
            acc += __shfl_xor_sync(0xffffffffu, acc, 2);
            acc += __shfl_xor_sync(0xffffffffu, acc, 4);
            if (cg == 0)
                op[(size_t)(c*CH + r) * Dd] = tf32r(acc);
        }
        if (more) {
            int nb = buf ^ 1;
            #pragma unroll
            for (int i = 0; i < 7; i++)
                if (lval[i]) *(float4*)&sh[nb][ldst[i]] = pf[i];
            __syncthreads();
            buf = nb;
        }
    }
}

// ---------------- launch ---------------------------------------------------
extern "C" void kernel_launch(void* const* d_in, const int* in_sizes, int n_in,
                              void* d_out, int out_size)
{
    const float* x     = (const float*)d_in[0];
    const float* Wq    = (const float*)d_in[1];
    const float* Wk    = (const float*)d_in[2];
    const float* Wv    = (const float*)d_in[3];
    const float* Qc    = (const float*)d_in[4];
    const float* Vc    = (const float*)d_in[5];
    const float* Wa_w  = (const float*)d_in[6];
    const float* Wa_b  = (const float*)d_in[7];
    const float* Wo    = (const float*)d_in[8];
    const float* gamma = (const float*)d_in[9];
    const float* beta  = (const float*)d_in[10];
    float* out = (float*)d_out;

    float *xn, *wall, *hw, *wo, *proj, *qv, *o;
    cudaGetSymbolAddress((void**)&xn,   g_xn);
    cudaGetSymbolAddress((void**)&wall, g_wall);
    cudaGetSymbolAddress((void**)&hw,   g_hw);
    cudaGetSymbolAddress((void**)&wo,   g_wo);
    cudaGetSymbolAddress((void**)&proj, g_proj);
    cudaGetSymbolAddress((void**)&qv,   g_qv);
    cudaGetSymbolAddress((void**)&o,    g_o);

    // 0: fused layernorm + weight prep
    ln_prep_kernel<<<Mm + PREP_BLOCKS, 256>>>(x, gamma, beta, Wq, Wk, Wv, Wa_w, Qc, Vc, Wo);
    // 1: projection GEMM + fused knorm/sigmoid epilogue
    gemm_tf32<<<dim3(PSTR/128, Mm/128), 128>>>(Dd, Dd, PSTR, 2, xn, wall, proj, nullptr, Wa_b);
    // 2: merged head GEMM: qv = [q_lat|v_lat] @ hw^T, K=64
    gemm_tf32<<<dim3(QVS/128, Mm/128), 128>>>(Cc, PSTR, QVS, 3, proj, hw, qv, nullptr, nullptr);
    // 3: recurrent scan (512 blocks; ncu slot 3 verifies the occupancy theory)
    scan_kernel<<<512, 128>>>();
    // 4: output GEMM + residual
    gemm_tf32<<<dim3(Dd/128, Mm/128), 128>>>(Dd, Dd, Dd, 1, o, wo, out, x, nullptr);
}

// round 16
// speedup vs baseline: 1.1475x; 1.1475x over previous
#include <cuda_runtime.h>
#include <cstdint>
#include <math.h>

// Problem constants
#define Bb   8
#define Tt   2048
#define Dd   1024
#define Hh   8
#define Cc   64
#define DVv  128
#define Mm   (Bb*Tt)
#define PSTR  768
#define CH   16
#define QVS  1536
#define NSEG 4
#define SEGT (Tt/NSEG)     // 512

// ---------------- scratch -------------------------------------------------
__device__ float g_xn  [(size_t)Mm*Dd];
__device__ float g_wall[(size_t)PSTR*Dd];
__device__ float g_hw  [(size_t)QVS*Cc];
__device__ float g_wo  [(size_t)Dd*Dd];
__device__ float g_proj[(size_t)Mm*PSTR];
__device__ float g_qv  [(size_t)Mm*QVS];
__device__ float g_o   [(size_t)Mm*Dd];
__device__ float g_qp  [(size_t)64*Tt*Cc];        // q ⊙ P, tf32 (segs 1-3 used)
__device__ float g_sf  [(size_t)64*NSEG*Cc*DVv];  // per-seg local final state [v*64+c]
__device__ float g_pf  [(size_t)64*NSEG*Cc];      // per-seg full decay product
__device__ float g_sinit[(size_t)64*3*Cc*DVv];    // combined init state segs 1-3, tf32

__device__ __forceinline__ uint32_t f2tf32(float f) {
    uint32_t u;
    asm volatile("cvt.rna.tf32.f32 %0, %1;" : "=r"(u) : "f"(f));
    return u;
}
__device__ __forceinline__ float tf32r(float f) { return __uint_as_float(f2tf32(f)); }

__device__ __forceinline__ uint32_t smem_u32(const void* p) {
    uint32_t a;
    asm("{ .reg .u64 t; cvta.to.shared.u64 t, %1; cvt.u32.u64 %0, t; }" : "=r"(a) : "l"(p));
    return a;
}
__device__ __forceinline__ void cp16(uint32_t dst, const void* src) {
    asm volatile("cp.async.cg.shared.global [%0], [%1], 16;" :: "r"(dst), "l"(src));
}
#define CP_COMMIT() asm volatile("cp.async.commit_group;" ::: "memory")
#define CP_WAIT(n)  asm volatile("cp.async.wait_group %0;" :: "n"(n) : "memory")

// ---------------- 1. fused LayerNorm + weight prep -------------------------
#define WALL_ELEMS (PSTR*Dd)
#define HW_ELEMS   (QVS*Cc)
#define WO_ELEMS   (Dd*Dd)
#define PREP_TOTAL (WALL_ELEMS + HW_ELEMS + WO_ELEMS)
#define PREP_BLOCKS ((PREP_TOTAL + 255) / 256)

__global__ __launch_bounds__(256)
void ln_prep_kernel(const float* __restrict__ x, const float* __restrict__ gamma,
                    const float* __restrict__ beta,
                    const float* __restrict__ Wq, const float* __restrict__ Wk,
                    const float* __restrict__ Wv, const float* __restrict__ Wa,
                    const float* __restrict__ Qc, const float* __restrict__ Vc,
                    const float* __restrict__ Wo)
{
    int tid = threadIdx.x;
    if (blockIdx.x >= Mm) {
        int i = (blockIdx.x - Mm) * 256 + tid;
        if (i < WALL_ELEMS) {
            int row = i >> 10, col = i & 1023;
            float val;
            if      (row <  64) val = Wq[(size_t)row       *1024 + col];
            else if (row < 128) val = Wk[(size_t)(row- 64) *1024 + col];
            else if (row < 192) val = Wv[(size_t)(row-128) *1024 + col];
            else if (row < 704) val = Wa[(size_t)(row-192) *1024 + col];
            else                val = 0.f;
            g_wall[i] = tf32r(val);
        } else if (i < WALL_ELEMS + HW_ELEMS) {
            int j = i - WALL_ELEMS;
            int n = j >> 6, c = j & 63;
            float val;
            if (n < 512) { int h = n >> 6, e = n & 63;  val = Qc[(size_t)h*Cc*Cc + (size_t)c*Cc + e]; }
            else { int nn = n - 512; int h = nn >> 7, d = nn & 127; val = Vc[(size_t)h*Cc*DVv + (size_t)c*DVv + d]; }
            g_hw[j] = tf32r(val);
        } else if (i < PREP_TOTAL) {
            int j = i - WALL_ELEMS - HW_ELEMS;
            g_wo[j] = tf32r(Wo[j]);
        }
        return;
    }

    int row = blockIdx.x;
    const float4* xr = (const float4*)(x + (size_t)row*Dd);
    float4 v = xr[tid];
    float s  = v.x + v.y + v.z + v.w;
    float s2 = v.x*v.x + v.y*v.y + v.z*v.z + v.w*v.w;
    #pragma unroll
    for (int o = 16; o > 0; o >>= 1) {
        s  += __shfl_xor_sync(0xffffffffu, s,  o);
        s2 += __shfl_xor_sync(0xffffffffu, s2, o);
    }
    __shared__ float r1[8], r2[8];
    int w = tid >> 5, l = tid & 31;
    if (l == 0) { r1[w] = s; r2[w] = s2; }
    __syncthreads();
    s = 0.f; s2 = 0.f;
    #pragma unroll
    for (int i = 0; i < 8; i++) { s += r1[i]; s2 += r2[i]; }
    float mu  = s * (1.f/Dd);
    float var = s2 * (1.f/Dd) - mu*mu;
    float inv = rsqrtf(var + 1e-5f);
    float4 g  = ((const float4*)gamma)[tid];
    float4 be = ((const float4*)beta)[tid];
    float4 o;
    o.x = tf32r((v.x - mu)*inv*g.x + be.x);
    o.y = tf32r((v.y - mu)*inv*g.y + be.y);
    o.z = tf32r((v.z - mu)*inv*g.z + be.z);
    o.w = tf32r((v.w - mu)*inv*g.w + be.w);
    ((float4*)(g_xn + (size_t)row*Dd))[tid] = o;
}

// ---------------- 2. TF32 GEMM (R12 form) + mode 5 correction batch -------
// mode 0 plain | 1 +resid | 2 proj epilogue | 3 head | 5 scan-correction
__device__ __forceinline__ void mma_tf32(float c[4], const uint32_t a[4], const uint32_t b[2]) {
    asm volatile(
        "mma.sync.aligned.m16n8k8.row.col.f32.tf32.tf32.f32 "
        "{%0,%1,%2,%3}, {%4,%5,%6,%7}, {%8,%9}, {%0,%1,%2,%3};\n"
        : "+f"(c[0]), "+f"(c[1]), "+f"(c[2]), "+f"(c[3])
        : "r"(a[0]), "r"(a[1]), "r"(a[2]), "r"(a[3]), "r"(b[0]), "r"(b[1]));
}

__global__ __launch_bounds__(128, 3)
void gemm_tf32(int K, int lda, int ldy, int mode,
               const float* __restrict__ A,
               const float* __restrict__ W,
               float* __restrict__ Y,
               const float* __restrict__ resid,
               const float* __restrict__ bias)
{
    __shared__ uint32_t As[2][128*20];
    __shared__ uint32_t Bs[2][128*20];

    int tid  = threadIdx.x;
    int lane = tid & 31, warp = tid >> 5;
    int wm = warp & 1, wn = warp >> 1;
    int g  = lane >> 2, tig = lane & 3;
    int row0 = blockIdx.y * 128;
    int col0 = blockIdx.x * 128;

    if (mode == 5) {
        // correction batch: blockIdx.y = bh*12 + (seg-1)*4 + mtile
        int y = blockIdx.y;
        int bhi = y / 12, r2 = y % 12;
        int sg = 1 + (r2 >> 2), mt = r2 & 3;
        int b = bhi >> 3, hh = bhi & 7;
        A = g_qp + ((size_t)bhi*Tt + sg*SEGT + mt*128) * 64;
        W = g_sinit + ((size_t)bhi*3 + (sg-1)) * (Cc*DVv);
        Y = g_o + ((size_t)(b*Tt) + sg*SEGT + mt*128) * Dd + hh*128;
        resid = Y;
        row0 = 0; col0 = 0;
    }
    if (mode == 3 && col0 >= 512) A += 128;

    uint32_t asb = smem_u32(As), bsb = smem_u32(Bs);
    const float* Abase = A + (size_t)row0 * lda;
    const float* Bbase = W + (size_t)col0 * K;

    float acc[4][8][4];
    #pragma unroll
    for (int i = 0; i < 4; i++)
        #pragma unroll
        for (int j = 0; j < 8; j++)
            #pragma unroll
            for (int e = 0; e < 4; e++) acc[i][j][e] = 0.f;

    #pragma unroll
    for (int i = 0; i < 4; i++) {
        int s = tid + i*128;
        int row = s >> 2, q = s & 3;
        uint32_t soff = (uint32_t)(row*20 + q*4) * 4;
        cp16(asb + soff, Abase + (size_t)row*lda + q*4);
        cp16(bsb + soff, Bbase + (size_t)row*K   + q*4);
    }
    CP_COMMIT();

    int NC = K >> 4;
    for (int c = 0; c < NC; c++) {
        int buf = c & 1;
        if (c + 1 < NC) {
            int nb = buf ^ 1;
            int k0 = (c + 1) << 4;
            uint32_t ab = asb + (uint32_t)nb * (128*20*4);
            uint32_t bb = bsb + (uint32_t)nb * (128*20*4);
            #pragma unroll
            for (int i = 0; i < 4; i++) {
                int s = tid + i*128;
                int row = s >> 2, q = s & 3;
                uint32_t soff = (uint32_t)(row*20 + q*4) * 4;
                cp16(ab + soff, Abase + (size_t)row*lda + k0 + q*4);
                cp16(bb + soff, Bbase + (size_t)row*K   + k0 + q*4);
            }
            CP_COMMIT();
            CP_WAIT(1);
        } else {
            CP_WAIT(0);
        }
        __syncthreads();

        const uint32_t* Ab  = As[buf];
        const uint32_t* Bb_ = Bs[buf];
        #pragma unroll
        for (int ks = 0; ks < 16; ks += 8) {
            uint32_t af[4][4], bf[8][2];
            #pragma unroll
            for (int i = 0; i < 4; i++) {
                int base = (wm*64 + i*16 + g)*20 + ks + tig;
                af[i][0] = Ab[base];
                af[i][1] = Ab[base + 8*20];
                af[i][2] = Ab[base + 4];
                af[i][3] = Ab[base + 8*20 + 4];
            }
            #pragma unroll
            for (int j = 0; j < 8; j++) {
                int base = (wn*64 + j*8 + g)*20 + ks + tig;
                bf[j][0] = Bb_[base];
                bf[j][1] = Bb_[base + 4];
            }
            #pragma unroll
            for (int i = 0; i < 4; i++)
                #pragma unroll
                for (int j = 0; j < 8; j++)
                    mma_tf32(acc[i][j], af[i], bf[j]);
        }
        __syncthreads();
    }

    bool knorm_warp = (mode == 2) && (col0 + wn*64 == 64);
    #pragma unroll
    for (int i = 0; i < 4; i++) {
        #pragma unroll
        for (int half = 0; half < 2; half++) {
            int m = row0 + wm*64 + i*16 + g + half*8;
            float scale = 1.f;
            if (knorm_warp) {
                float s = 0.f;
                #pragma unroll
                for (int j = 0; j < 8; j++) {
                    float e0 = acc[i][j][half*2], e1 = acc[i][j][half*2+1];
                    s = fmaf(e0, e0, s); s = fmaf(e1, e1, s);
                }
                s += __shfl_xor_sync(0xffffffffu, s, 1);
                s += __shfl_xor_sync(0xffffffffu, s, 2);
                scale = 1.f / fmaxf(sqrtf(s), 1e-12f);
            }
            #pragma unroll
            for (int j = 0; j < 8; j++) {
                int n0 = col0 + wn*64 + j*8 + tig*2;
                float2 val = make_float2(acc[i][j][half*2], acc[i][j][half*2+1]);
                if (mode == 1 || mode == 5) {
                    const float2 r = *(const float2*)(resid + (size_t)m*ldy + n0);
                    val.x += r.x; val.y += r.y;
                    if (mode == 5) { val.x = tf32r(val.x); val.y = tf32r(val.y); }
                } else if (mode == 2) {
                    if (knorm_warp) {
                        val.x *= scale; val.y *= scale;
                    } else if (n0 < 192) {
                        val.x = tf32r(val.x); val.y = tf32r(val.y);
                    } else if (n0 < 704) {
                        float2 bb = *(const float2*)(bias + n0 - 192);
                        val.x = 1.f / (1.f + expf(-(val.x + bb.x)));
                        val.y = 1.f / (1.f + expf(-(val.y + bb.y)));
                    }
                }
                *(float2*)(Y + (size_t)m*ldy + n0) = val;
            }
        }
    }
}

// ---------------- 3a. segmented scan pass A --------------------------------
// 512 blocks = seg(4) x bh(64) x vhalf(2). Thread = (vg 0..31 v-pair, cg 0..7).
// Local scan over SEGT steps from S=0; tracks P (decay product); stores
// o_local (seg0 rounded, else raw), QP=q*P (tf32, vhalf0, seg>0), Sf, Pfull.
__global__ __launch_bounds__(256, 3)
void scanA_kernel()
{
    int blk   = blockIdx.x;
    int seg   = blk >> 7;
    int sub   = blk & 127;
    int bh    = sub >> 1;
    int vhalf = sub & 1;
    int b = bh >> 3, h = bh & 7;
    int tid = threadIdx.x;
    int vg  = tid >> 3;
    int cg  = tid & 7;
    int t0  = seg * SEGT;
    const float* qp_ = g_qv + (size_t)(b*Tt + t0)*QVS + h*64;
    const float* vp  = g_qv + (size_t)(b*Tt + t0)*QVS + 512 + h*128 + vhalf*64;
    const float* pp  = g_proj + (size_t)(b*Tt + t0) * PSTR;
    float* op = g_o + (size_t)(b*Tt + t0) * Dd + h*DVv + vhalf*64 + vg*2;

    const float* lsrc[4];
    size_t ladv[4];
    int ldst[4];
    #pragma unroll
    for (int i = 0; i < 4; i++) {
        int f = i * 256 + tid;
        int lq4 = f & 15, ls = (f >> 4) & 3, lr = f >> 6;
        switch (ls) {
            case 0:  lsrc[i] = pp + (size_t)lr*PSTR + 192 + h*64 + lq4*4; ladv[i] = (size_t)CH*PSTR; break;
            case 1:  lsrc[i] = pp + (size_t)lr*PSTR + 64 + lq4*4;         ladv[i] = (size_t)CH*PSTR; break;
            case 2:  lsrc[i] = qp_ + (size_t)lr*QVS + lq4*4;              ladv[i] = (size_t)CH*QVS;  break;
            default: lsrc[i] = vp + (size_t)lr*QVS + lq4*4;               ladv[i] = (size_t)CH*QVS;  break;
        }
        ldst[i] = (lr*4 + ls)*64 + lq4*4;
    }

    __shared__ __align__(16) float sh[2][CH*256];
    __shared__ __align__(16) float qps[CH*64];
    float S0[8], S1[8], P[8];
    #pragma unroll
    for (int i = 0; i < 8; i++) { S0[i] = 0.f; S1[i] = 0.f; P[i] = 1.f; }

    #pragma unroll
    for (int i = 0; i < 4; i++)
        *(float4*)&sh[0][ldst[i]] = *(const float4*)lsrc[i];
    __syncthreads();

    int NCH = SEGT / CH;
    int buf = 0;
    for (int c = 0; c < NCH; c++) {
        float4 pf[4];
        bool more = (c + 1) < NCH;
        if (more) {
            #pragma unroll
            for (int i = 0; i < 4; i++)
                pf[i] = *(const float4*)(lsrc[i] + (size_t)(c+1)*ladv[i]);
        }
        const float* cb = sh[buf];
        #pragma unroll 4
        for (int r = 0; r < CH; r++) {
            const float* base = cb + r*256;
            float4 a0 = *(const float4*)(base +       cg*8);
            float4 a1 = *(const float4*)(base +       cg*8 + 4);
            float4 k0 = *(const float4*)(base +  64 + cg*8);
            float4 k1 = *(const float4*)(base +  64 + cg*8 + 4);
            float4 q0 = *(const float4*)(base + 128 + cg*8);
            float4 q1 = *(const float4*)(base + 128 + cg*8 + 4);
            float2 vt = *(const float2*)(base + 192 + vg*2);
            float acc0 = 0.f, acc1 = 0.f;

            P[0] *= a0.x; P[1] *= a0.y; P[2] *= a0.z; P[3] *= a0.w;
            P[4] *= a1.x; P[5] *= a1.y; P[6] *= a1.z; P[7] *= a1.w;

            S0[0] = fmaf(a0.x, S0[0], k0.x*vt.x); acc0 = fmaf(q0.x, S0[0], acc0);
            S1[0] = fmaf(a0.x, S1[0], k0.x*vt.y); acc1 = fmaf(q0.x, S1[0], acc1);
            S0[1] = fmaf(a0.y, S0[1], k0.y*vt.x); acc0 = fmaf(q0.y, S0[1], acc0);
            S1[1] = fmaf(a0.y, S1[1], k0.y*vt.y); acc1 = fmaf(q0.y, S1[1], acc1);
            S0[2] = fmaf(a0.z, S0[2], k0.z*vt.x); acc0 = fmaf(q0.z, S0[2], acc0);
            S1[2] = fmaf(a0.z, S1[2], k0.z*vt.y); acc1 = fmaf(q0.z, S1[2], acc1);
            S0[3] = fmaf(a0.w, S0[3], k0.w*vt.x); acc0 = fmaf(q0.w, S0[3], acc0);
            S1[3] = fmaf(a0.w, S1[3], k0.w*vt.y); acc1 = fmaf(q0.w, S1[3], acc1);
            S0[4] = fmaf(a1.x, S0[4], k1.x*vt.x); acc0 = fmaf(q1.x, S0[4], acc0);
            S1[4] = fmaf(a1.x, S1[4], k1.x*vt.y); acc1 = fmaf(q1.x, S1[4], acc1);
            S0[5] = fmaf(a1.y, S0[5], k1.y*vt.x); acc0 = fmaf(q1.y, S0[5], acc0);
            S1[5] = fmaf(a1.y, S1[5], k1.y*vt.y); acc1 = fmaf(q1.y, S1[5], acc1);
            S0[6] = fmaf(a1.z, S0[6], k1.z*vt.x); acc0 = fmaf(q1.z, S0[6], acc0);
            S1[6] = fmaf(a1.z, S1[6], k1.z*vt.y); acc1 = fmaf(q1.z, S1[6], acc1);
            S0[7] = fmaf(a1.w, S0[7], k1.w*vt.x); acc0 = fmaf(q1.w, S0[7], acc0);
            S1[7] = fmaf(a1.w, S1[7], k1.w*vt.y); acc1 = fmaf(q1.w, S1[7], acc1);

            // QP for correction GEMM (one writer per c)
            if (vg == 0) {
                float* qd = &qps[r*64 + cg*8];
                qd[0] = q0.x*P[0]; qd[1] = q0.y*P[1]; qd[2] = q0.z*P[2]; qd[3] = q0.w*P[3];
                qd[4] = q1.x*P[4]; qd[5] = q1.y*P[5]; qd[6] = q1.z*P[6]; qd[7] = q1.w*P[7];
            }

            acc0 += __shfl_xor_sync(0xffffffffu, acc0, 1);
            acc1 += __shfl_xor_sync(0xffffffffu, acc1, 1);
            acc0 += __shfl_xor_sync(0xffffffffu, acc0, 2);
            acc1 += __shfl_xor_sync(0xffffffffu, acc1, 2);
            acc0 += __shfl_xor_sync(0xffffffffu, acc0, 4);
            acc1 += __shfl_xor_sync(0xffffffffu, acc1, 4);
            if (cg == 0) {
                float2 ov;
                if (seg == 0) ov = make_float2(tf32r(acc0), tf32r(acc1));
                else          ov = make_float2(acc0, acc1);   // rounded after corr add
                *(float2*)(op + (size_t)(c*CH + r) * Dd) = ov;
            }
        }
        __syncthreads();
        // dump QP chunk (tf32) — one vhalf writes, segs 1..3 only
        if (vhalf == 0 && seg > 0) {
            int r = tid >> 4, o4 = (tid & 15) * 4;
            float4 qv4 = *(const float4*)&qps[r*64 + o4];
            qv4 = make_float4(tf32r(qv4.x), tf32r(qv4.y), tf32r(qv4.z), tf32r(qv4.w));
            *(float4*)&g_qp[((size_t)bh*Tt + t0 + c*CH + r)*64 + o4] = qv4;
        }
        if (more) {
            int nb = buf ^ 1;
            #pragma unroll
            for (int i = 0; i < 4; i++)
                *(float4*)&sh[nb][ldst[i]] = pf[i];
            __syncthreads();
            buf = nb;
        }
    }

    // store local final state Sf [v*64 + c] and Pfull
    {
        float* sf = g_sf + (size_t)(bh*NSEG + seg) * (Cc*DVv);
        int v0 = vhalf*64 + vg*2;
        *(float4*)&sf[(size_t)v0*64 + cg*8]     = make_float4(S0[0], S0[1], S0[2], S0[3]);
        *(float4*)&sf[(size_t)v0*64 + cg*8 + 4] = make_float4(S0[4], S0[5], S0[6], S0[7]);
        *(float4*)&sf[(size_t)(v0+1)*64 + cg*8]     = make_float4(S1[0], S1[1], S1[2], S1[3]);
        *(float4*)&sf[(size_t)(v0+1)*64 + cg*8 + 4] = make_float4(S1[4], S1[5], S1[6], S1[7]);
        if (vhalf == 0 && vg == 0) {
            float* pfp = g_pf + (size_t)(bh*NSEG + seg) * Cc;
            *(float4*)&pfp[cg*8]     = make_float4(P[0], P[1], P[2], P[3]);
            *(float4*)&pfp[cg*8 + 4] = make_float4(P[4], P[5], P[6], P[7]);
        }
    }
}

// ---------------- 3b. combine segment states -------------------------------
// Sinit_1 = Sf0; Sinit_{j+1} = Sf_j + Pfull_j * Sinit_j  (tf32-rounded stores)
__global__ __launch_bounds__(256)
void combine_kernel()
{
    int bh = blockIdx.x;
    int tid = threadIdx.x;
    const float* sf = g_sf + (size_t)bh*NSEG*(Cc*DVv);
    const float* pf = g_pf + (size_t)bh*NSEG*Cc;
    float* si = g_sinit + (size_t)bh*3*(Cc*DVv);
    #pragma unroll
    for (int i = 0; i < (Cc*DVv/4)/256; i++) {   // 8 float4 per thread
        int idx = tid + i*256;
        int c0 = (idx*4) & 63;
        float4 run = *(const float4*)&sf[idx*4];                 // Sf0
        *(float4*)&si[idx*4] = make_float4(tf32r(run.x), tf32r(run.y), tf32r(run.z), tf32r(run.w));
        #pragma unroll
        for (int j = 1; j < 3; j++) {
            float4 sfe = *(const float4*)&sf[(size_t)j*(Cc*DVv) + idx*4];
            float4 pfe = *(const float4*)&pf[(size_t)j*Cc + c0];
            run.x = sfe.x + pfe.x*run.x;
            run.y = sfe.y + pfe.y*run.y;
            run.z = sfe.z + pfe.z*run.z;
            run.w = sfe.w + pfe.w*run.w;
            *(float4*)&si[(size_t)j*(Cc*DVv) + idx*4] =
                make_float4(tf32r(run.x), tf32r(run.y), tf32r(run.z), tf32r(run.w));
        }
    }
}

// ---------------- launch ---------------------------------------------------
extern "C" void kernel_launch(void* const* d_in, const int* in_sizes, int n_in,
                              void* d_out, int out_size)
{
    const float* x     = (const float*)d_in[0];
    const float* Wq    = (const float*)d_in[1];
    const float* Wk    = (const float*)d_in[2];
    const float* Wv    = (const float*)d_in[3];
    const float* Qc    = (const float*)d_in[4];
    const float* Vc    = (const float*)d_in[5];
    const float* Wa_w  = (const float*)d_in[6];
    const float* Wa_b  = (const float*)d_in[7];
    const float* Wo    = (const float*)d_in[8];
    const float* gamma = (const float*)d_in[9];
    const float* beta  = (const float*)d_in[10];
    float* out = (float*)d_out;

    float *xn, *wall, *hw, *wo, *proj, *qv, *o;
    cudaGetSymbolAddress((void**)&xn,   g_xn);
    cudaGetSymbolAddress((void**)&wall, g_wall);
    cudaGetSymbolAddress((void**)&hw,   g_hw);
    cudaGetSymbolAddress((void**)&wo,   g_wo);
    cudaGetSymbolAddress((void**)&proj, g_proj);
    cudaGetSymbolAddress((void**)&qv,   g_qv);
    cudaGetSymbolAddress((void**)&o,    g_o);

    // 0: fused layernorm + weight prep
    ln_prep_kernel<<<Mm + PREP_BLOCKS, 256>>>(x, gamma, beta, Wq, Wk, Wv, Wa_w, Qc, Vc, Wo);
    // 1: projection GEMM + fused knorm/sigmoid epilogue
    gemm_tf32<<<dim3(PSTR/128, Mm/128), 128>>>(Dd, Dd, PSTR, 2, xn, wall, proj, nullptr, Wa_b);
    // 2: merged head GEMM
    gemm_tf32<<<dim3(QVS/128, Mm/128), 128>>>(Cc, PSTR, QVS, 3, proj, hw, qv, nullptr, nullptr);
    // 3: segmented scan pass A (512 blocks — ncu slot 3)
    scanA_kernel<<<NSEG*128, 256>>>();
    // 4: combine per-segment states
    combine_kernel<<<64, 256>>>();
    // 5: correction GEMM: o[segs 1-3] += QP @ Sinit  (rounds after add)
    gemm_tf32<<<dim3(1, 64*12), 128>>>(Cc, Cc, Dd, 5, nullptr, nullptr, nullptr, nullptr, nullptr);
    // 6: output GEMM + residual
    gemm_tf32<<<dim3(Dd/128, Mm/128), 128>>>(Dd, Dd, Dd, 1, o, wo, out, x, nullptr);
}

// round 17
// speedup vs baseline: 1.3837x; 1.2059x over previous
#include <cuda_runtime.h>
#include <cstdint>
#include <math.h>

// Problem constants
#define Bb   8
#define Tt   2048
#define Dd   1024
#define Hh   8
#define Cc   64
#define DVv  128
#define Mm   (Bb*Tt)
#define PSTR  768
#define CH   16
#define QVS  1536

// ---------------- scratch -------------------------------------------------
__device__ float g_xn  [(size_t)Mm*Dd];       // tf32-rounded layernorm out
__device__ float g_wall[(size_t)PSTR*Dd];     // tf32-rounded proj weights
__device__ float g_hw  [(size_t)QVS*Cc];      // tf32-rounded head weights
__device__ float g_wo  [(size_t)Dd*Dd];       // tf32-rounded output weights
__device__ float g_proj[(size_t)Mm*PSTR];     // qlat|kn|vlat|alpha (q/v tf32-rounded)
__device__ float g_qv  [(size_t)Mm*QVS];
__device__ float g_o   [(size_t)Mm*Dd];       // tf32-rounded scan out

__device__ __forceinline__ uint32_t f2tf32(float f) {
    uint32_t u;
    asm volatile("cvt.rna.tf32.f32 %0, %1;" : "=r"(u) : "f"(f));
    return u;
}
__device__ __forceinline__ float tf32r(float f) { return __uint_as_float(f2tf32(f)); }

__device__ __forceinline__ uint32_t smem_u32(const void* p) {
    uint32_t a;
    asm("{ .reg .u64 t; cvta.to.shared.u64 t, %1; cvt.u32.u64 %0, t; }" : "=r"(a) : "l"(p));
    return a;
}
__device__ __forceinline__ void cp16(uint32_t dst, const void* src) {
    asm volatile("cp.async.cg.shared.global [%0], [%1], 16;" :: "r"(dst), "l"(src));
}
#define CP_COMMIT() asm volatile("cp.async.commit_group;" ::: "memory")
#define CP_WAIT(n)  asm volatile("cp.async.wait_group %0;" :: "n"(n) : "memory")

// ---------------- 1. fused LayerNorm + weight prep -------------------------
#define WALL_ELEMS (PSTR*Dd)
#define HW_ELEMS   (QVS*Cc)
#define WO_ELEMS   (Dd*Dd)
#define PREP_TOTAL (WALL_ELEMS + HW_ELEMS + WO_ELEMS)
#define PREP_BLOCKS ((PREP_TOTAL + 255) / 256)

__global__ __launch_bounds__(256)
void ln_prep_kernel(const float* __restrict__ x, const float* __restrict__ gamma,
                    const float* __restrict__ beta,
                    const float* __restrict__ Wq, const float* __restrict__ Wk,
                    const float* __restrict__ Wv, const float* __restrict__ Wa,
                    const float* __restrict__ Qc, const float* __restrict__ Vc,
                    const float* __restrict__ Wo)
{
    int tid = threadIdx.x;
    if (blockIdx.x >= Mm) {
        int i = (blockIdx.x - Mm) * 256 + tid;
        if (i < WALL_ELEMS) {
            int row = i >> 10, col = i & 1023;
            float val;
            if      (row <  64) val = Wq[(size_t)row       *1024 + col];
            else if (row < 128) val = Wk[(size_t)(row- 64) *1024 + col];
            else if (row < 192) val = Wv[(size_t)(row-128) *1024 + col];
            else if (row < 704) val = Wa[(size_t)(row-192) *1024 + col];
            else                val = 0.f;
            g_wall[i] = tf32r(val);
        } else if (i < WALL_ELEMS + HW_ELEMS) {
            int j = i - WALL_ELEMS;
            int n = j >> 6, c = j & 63;
            float val;
            if (n < 512) { int h = n >> 6, e = n & 63;  val = Qc[(size_t)h*Cc*Cc + (size_t)c*Cc + e]; }
            else { int nn = n - 512; int h = nn >> 7, d = nn & 127; val = Vc[(size_t)h*Cc*DVv + (size_t)c*DVv + d]; }
            g_hw[j] = tf32r(val);
        } else if (i < PREP_TOTAL) {
            int j = i - WALL_ELEMS - HW_ELEMS;
            g_wo[j] = tf32r(Wo[j]);
        }
        return;
    }

    int row = blockIdx.x;
    const float4* xr = (const float4*)(x + (size_t)row*Dd);
    float4 v = xr[tid];
    float s  = v.x + v.y + v.z + v.w;
    float s2 = v.x*v.x + v.y*v.y + v.z*v.z + v.w*v.w;
    #pragma unroll
    for (int o = 16; o > 0; o >>= 1) {
        s  += __shfl_xor_sync(0xffffffffu, s,  o);
        s2 += __shfl_xor_sync(0xffffffffu, s2, o);
    }
    __shared__ float r1[8], r2[8];
    int w = tid >> 5, l = tid & 31;
    if (l == 0) { r1[w] = s; r2[w] = s2; }
    __syncthreads();
    s = 0.f; s2 = 0.f;
    #pragma unroll
    for (int i = 0; i < 8; i++) { s += r1[i]; s2 += r2[i]; }
    float mu  = s * (1.f/Dd);
    float var = s2 * (1.f/Dd) - mu*mu;
    float inv = rsqrtf(var + 1e-5f);
    float4 g  = ((const float4*)gamma)[tid];
    float4 be = ((const float4*)beta)[tid];
    float4 o;
    o.x = tf32r((v.x - mu)*inv*g.x + be.x);
    o.y = tf32r((v.y - mu)*inv*g.y + be.y);
    o.z = tf32r((v.z - mu)*inv*g.z + be.z);
    o.w = tf32r((v.w - mu)*inv*g.w + be.w);
    ((float4*)(g_xn + (size_t)row*Dd))[tid] = o;
}

// ---------------- 2. TF32 GEMM, 64x64 warp tile, cp.async (R12 form) ------
__device__ __forceinline__ void mma_tf32(float c[4], const uint32_t a[4], const uint32_t b[2]) {
    asm volatile(
        "mma.sync.aligned.m16n8k8.row.col.f32.tf32.tf32.f32 "
        "{%0,%1,%2,%3}, {%4,%5,%6,%7}, {%8,%9}, {%0,%1,%2,%3};\n"
        : "+f"(c[0]), "+f"(c[1]), "+f"(c[2]), "+f"(c[3])
        : "r"(a[0]), "r"(a[1]), "r"(a[2]), "r"(a[3]), "r"(b[0]), "r"(b[1]));
}

__global__ __launch_bounds__(128, 3)
void gemm_tf32(int K, int lda, int ldy, int mode,
               const float* __restrict__ A,
               const float* __restrict__ W,
               float* __restrict__ Y,
               const float* __restrict__ resid,
               const float* __restrict__ bias)
{
    __shared__ uint32_t As[2][128*20];
    __shared__ uint32_t Bs[2][128*20];

    int tid  = threadIdx.x;
    int lane = tid & 31, warp = tid >> 5;
    int wm = warp & 1, wn = warp >> 1;
    int g  = lane >> 2, tig = lane & 3;
    int row0 = blockIdx.y * 128;
    int col0 = blockIdx.x * 128;
    if (mode == 3 && col0 >= 512) A += 128;

    uint32_t asb = smem_u32(As), bsb = smem_u32(Bs);
    const float* Abase = A + (size_t)row0 * lda;
    const float* Bbase = W + (size_t)col0 * K;

    float acc[4][8][4];
    #pragma unroll
    for (int i = 0; i < 4; i++)
        #pragma unroll
        for (int j = 0; j < 8; j++)
            #pragma unroll
            for (int e = 0; e < 4; e++) acc[i][j][e] = 0.f;

    #pragma unroll
    for (int i = 0; i < 4; i++) {
        int s = tid + i*128;
        int row = s >> 2, q = s & 3;
        uint32_t soff = (uint32_t)(row*20 + q*4) * 4;
        cp16(asb + soff, Abase + (size_t)row*lda + q*4);
        cp16(bsb + soff, Bbase + (size_t)row*K   + q*4);
    }
    CP_COMMIT();

    int NC = K >> 4;
    for (int c = 0; c < NC; c++) {
        int buf = c & 1;
        if (c + 1 < NC) {
            int nb = buf ^ 1;
            int k0 = (c + 1) << 4;
            uint32_t ab = asb + (uint32_t)nb * (128*20*4);
            uint32_t bb = bsb + (uint32_t)nb * (128*20*4);
            #pragma unroll
            for (int i = 0; i < 4; i++) {
                int s = tid + i*128;
                int row = s >> 2, q = s & 3;
                uint32_t soff = (uint32_t)(row*20 + q*4) * 4;
                cp16(ab + soff, Abase + (size_t)row*lda + k0 + q*4);
                cp16(bb + soff, Bbase + (size_t)row*K   + k0 + q*4);
            }
            CP_COMMIT();
            CP_WAIT(1);
        } else {
            CP_WAIT(0);
        }
        __syncthreads();

        const uint32_t* Ab  = As[buf];
        const uint32_t* Bb_ = Bs[buf];
        #pragma unroll
        for (int ks = 0; ks < 16; ks += 8) {
            uint32_t af[4][4], bf[8][2];
            #pragma unroll
            for (int i = 0; i < 4; i++) {
                int base = (wm*64 + i*16 + g)*20 + ks + tig;
                af[i][0] = Ab[base];
                af[i][1] = Ab[base + 8*20];
                af[i][2] = Ab[base + 4];
                af[i][3] = Ab[base + 8*20 + 4];
            }
            #pragma unroll
            for (int j = 0; j < 8; j++) {
                int base = (wn*64 + j*8 + g)*20 + ks + tig;
                bf[j][0] = Bb_[base];
                bf[j][1] = Bb_[base + 4];
            }
            #pragma unroll
            for (int i = 0; i < 4; i++)
                #pragma unroll
                for (int j = 0; j < 8; j++)
                    mma_tf32(acc[i][j], af[i], bf[j]);
        }
        __syncthreads();
    }

    bool knorm_warp = (mode == 2) && (col0 + wn*64 == 64);
    #pragma unroll
    for (int i = 0; i < 4; i++) {
        #pragma unroll
        for (int half = 0; half < 2; half++) {
            int m = row0 + wm*64 + i*16 + g + half*8;
            float scale = 1.f;
            if (knorm_warp) {
                float s = 0.f;
                #pragma unroll
                for (int j = 0; j < 8; j++) {
                    float e0 = acc[i][j][half*2], e1 = acc[i][j][half*2+1];
                    s = fmaf(e0, e0, s); s = fmaf(e1, e1, s);
                }
                s += __shfl_xor_sync(0xffffffffu, s, 1);
                s += __shfl_xor_sync(0xffffffffu, s, 2);
                scale = 1.f / fmaxf(sqrtf(s), 1e-12f);
            }
            #pragma unroll
            for (int j = 0; j < 8; j++) {
                int n0 = col0 + wn*64 + j*8 + tig*2;
                float2 val = make_float2(acc[i][j][half*2], acc[i][j][half*2+1]);
                if (mode == 1) {
                    const float2 r = *(const float2*)(resid + (size_t)m*ldy + n0);
                    val.x += r.x; val.y += r.y;
                } else if (mode == 2) {
                    if (knorm_warp) {
                        val.x *= scale; val.y *= scale;
                    } else if (n0 < 192) {
                        val.x = tf32r(val.x); val.y = tf32r(val.y);
                    } else if (n0 < 704) {
                        float2 bb = *(const float2*)(bias + n0 - 192);
                        val.x = 1.f / (1.f + expf(-(val.x + bb.x)));
                        val.y = 1.f / (1.f + expf(-(val.y + bb.y)));
                    }
                }
                *(float2*)(Y + (size_t)m*ldy + n0) = val;
            }
        }
    }
}

// ---------------- 3. recurrent scan (8c x 2v, split acc chains) ------------
__global__ __launch_bounds__(256)
void scan_kernel()
{
    int blk   = blockIdx.x;
    int bh    = blk >> 1;
    int vhalf = blk & 1;
    int b = bh >> 3, h = bh & 7;
    int tid = threadIdx.x;
    int vg  = tid >> 3;
    int cg  = tid & 7;
    const float* qp = g_qv + (size_t)(b*Tt)*QVS + h*64;
    const float* vp = g_qv + (size_t)(b*Tt)*QVS + 512 + h*128 + vhalf*64;
    const float* pp = g_proj + (size_t)b * Tt * PSTR;
    float* op = g_o + (size_t)b * Tt * Dd + h*DVv + vhalf*64 + vg*2;

    const float* lsrc[4];
    size_t ladv[4];
    int ldst[4];
    #pragma unroll
    for (int i = 0; i < 4; i++) {
        int f = i * 256 + tid;
        int lq4 = f & 15, ls = (f >> 4) & 3, lr = f >> 6;
        switch (ls) {
            case 0:  lsrc[i] = pp + (size_t)lr*PSTR + 192 + h*64 + lq4*4; ladv[i] = (size_t)CH*PSTR; break;
            case 1:  lsrc[i] = pp + (size_t)lr*PSTR + 64 + lq4*4;         ladv[i] = (size_t)CH*PSTR; break;
            case 2:  lsrc[i] = qp + (size_t)lr*QVS + lq4*4;               ladv[i] = (size_t)CH*QVS;  break;
            default: lsrc[i] = vp + (size_t)lr*QVS + lq4*4;               ladv[i] = (size_t)CH*QVS;  break;
        }
        ldst[i] = (lr*4 + ls)*64 + lq4*4;
    }

    __shared__ __align__(16) float sh[2][CH*256];
    float S0[8], S1[8];
    #pragma unroll
    for (int i = 0; i < 8; i++) { S0[i] = 0.f; S1[i] = 0.f; }

    #pragma unroll
    for (int i = 0; i < 4; i++)
        *(float4*)&sh[0][ldst[i]] = *(const float4*)lsrc[i];
    __syncthreads();

    int buf = 0;
    for (int c = 0; c < Tt/CH; c++) {
        float4 pf[4];
        bool more = (c + 1) < (Tt/CH);
        if (more) {
            #pragma unroll
            for (int i = 0; i < 4; i++)
                pf[i] = *(const float4*)(lsrc[i] + (size_t)(c+1)*ladv[i]);
        }
        const float* cb = sh[buf];
        #pragma unroll 8
        for (int r = 0; r < CH; r++) {
            const float* base = cb + r*256;
            float4 a0 = *(const float4*)(base +       cg*8);
            float4 a1 = *(const float4*)(base +       cg*8 + 4);
            float4 k0 = *(const float4*)(base +  64 + cg*8);
            float4 k1 = *(const float4*)(base +  64 + cg*8 + 4);
            float4 q0 = *(const float4*)(base + 128 + cg*8);
            float4 q1 = *(const float4*)(base + 128 + cg*8 + 4);
            float2 vt = *(const float2*)(base + 192 + vg*2);
            // split partial accumulators: two independent 4-FMA chains per output
            float a0a = 0.f, a0b = 0.f, a1a = 0.f, a1b = 0.f;

            S0[0] = fmaf(a0.x, S0[0], k0.x*vt.x); a0a = fmaf(q0.x, S0[0], a0a);
            S1[0] = fmaf(a0.x, S1[0], k0.x*vt.y); a1a = fmaf(q0.x, S1[0], a1a);
            S0[1] = fmaf(a0.y, S0[1], k0.y*vt.x); a0a = fmaf(q0.y, S0[1], a0a);
            S1[1] = fmaf(a0.y, S1[1], k0.y*vt.y); a1a = fmaf(q0.y, S1[1], a1a);
            S0[2] = fmaf(a0.z, S0[2], k0.z*vt.x); a0a = fmaf(q0.z, S0[2], a0a);
            S1[2] = fmaf(a0.z, S1[2], k0.z*vt.y); a1a = fmaf(q0.z, S1[2], a1a);
            S0[3] = fmaf(a0.w, S0[3], k0.w*vt.x); a0a = fmaf(q0.w, S0[3], a0a);
            S1[3] = fmaf(a0.w, S1[3], k0.w*vt.y); a1a = fmaf(q0.w, S1[3], a1a);
            S0[4] = fmaf(a1.x, S0[4], k1.x*vt.x); a0b = fmaf(q1.x, S0[4], a0b);
            S1[4] = fmaf(a1.x, S1[4], k1.x*vt.y); a1b = fmaf(q1.x, S1[4], a1b);
            S0[5] = fmaf(a1.y, S0[5], k1.y*vt.x); a0b = fmaf(q1.y, S0[5], a0b);
            S1[5] = fmaf(a1.y, S1[5], k1.y*vt.y); a1b = fmaf(q1.y, S1[5], a1b);
            S0[6] = fmaf(a1.z, S0[6], k1.z*vt.x); a0b = fmaf(q1.z, S0[6], a0b);
            S1[6] = fmaf(a1.z, S1[6], k1.z*vt.y); a1b = fmaf(q1.z, S1[6], a1b);
            S0[7] = fmaf(a1.w, S0[7], k1.w*vt.x); a0b = fmaf(q1.w, S0[7], a0b);
            S1[7] = fmaf(a1.w, S1[7], k1.w*vt.y); a1b = fmaf(q1.w, S1[7], a1b);

            float acc0 = a0a + a0b;
            float acc1 = a1a + a1b;
            acc0 += __shfl_xor_sync(0xffffffffu, acc0, 1);
            acc1 += __shfl_xor_sync(0xffffffffu, acc1, 1);
            acc0 += __shfl_xor_sync(0xffffffffu, acc0, 2);
            acc1 += __shfl_xor_sync(0xffffffffu, acc1, 2);
            acc0 += __shfl_xor_sync(0xffffffffu, acc0, 4);
            acc1 += __shfl_xor_sync(0xffffffffu, acc1, 4);
            if (cg == 0)
                *(float2*)(op + (size_t)(c*CH + r) * Dd) = make_float2(tf32r(acc0), tf32r(acc1));
        }
        if (more) {
            int nb = buf ^ 1;
            #pragma unroll
            for (int i = 0; i < 4; i++)
                *(float4*)&sh[nb][ldst[i]] = pf[i];
            __syncthreads();
            buf = nb;
        }
    }
}

// ---------------- launch ---------------------------------------------------
extern "C" void kernel_launch(void* const* d_in, const int* in_sizes, int n_in,
                              void* d_out, int out_size)
{
    const float* x     = (const float*)d_in[0];
    const float* Wq    = (const float*)d_in[1];
    const float* Wk    = (const float*)d_in[2];
    const float* Wv    = (const float*)d_in[3];
    const float* Qc    = (const float*)d_in[4];
    const float* Vc    = (const float*)d_in[5];
    const float* Wa_w  = (const float*)d_in[6];
    const float* Wa_b  = (const float*)d_in[7];
    const float* Wo    = (const float*)d_in[8];
    const float* gamma = (const float*)d_in[9];
    const float* beta  = (const float*)d_in[10];
    float* out = (float*)d_out;

    float *xn, *wall, *hw, *wo, *proj, *qv, *o;
    cudaGetSymbolAddress((void**)&xn,   g_xn);
    cudaGetSymbolAddress((void**)&wall, g_wall);
    cudaGetSymbolAddress((void**)&hw,   g_hw);
    cudaGetSymbolAddress((void**)&wo,   g_wo);
    cudaGetSymbolAddress((void**)&proj, g_proj);
    cudaGetSymbolAddress((void**)&qv,   g_qv);
    cudaGetSymbolAddress((void**)&o,    g_o);

    // 0: fused layernorm + weight prep
    ln_prep_kernel<<<Mm + PREP_BLOCKS, 256>>>(x, gamma, beta, Wq, Wk, Wv, Wa_w, Qc, Vc, Wo);
    // 1: projection GEMM + fused knorm/sigmoid epilogue
    gemm_tf32<<<dim3(PSTR/128, Mm/128), 128>>>(Dd, Dd, PSTR, 2, xn, wall, proj, nullptr, Wa_b);
    // 2: merged head GEMM: qv = [q_lat|v_lat] @ hw^T, K=64
    gemm_tf32<<<dim3(QVS/128, Mm/128), 128>>>(Cc, PSTR, QVS, 3, proj, hw, qv, nullptr, nullptr);
    // 3: recurrent scan (ncu slot 3)
    scan_kernel<<<128, 256>>>();
    // 4: output GEMM + residual
    gemm_tf32<<<dim3(Dd/128, Mm/128), 128>>>(Dd, Dd, Dd, 1, o, wo, out, x, nullptr);
}